// round 4
// baseline (speedup 1.0000x reference)
#include <cuda_runtime.h>
#include <cuda_fp16.h>

#define DIM       128
#define UP        132          // padded sU row stride (floats), multiple of 4 for float4
#define NTHREADS  256

// shared memory layout (float offsets)
#define OFF_PIT   0                       // Pi^T  [k][j], 128x128
#define OFF_PI    (DIM * DIM)             // Pi    [j][k], 128x128
#define OFF_U     (2 * DIM * DIM)         // x tile / quantized values, 128xUP
#define OFF_INV   (OFF_U + DIM * UP)      // 1/(norm+1e-8) per row
#define OFF_NQ    (OFF_INV + DIM)         // fp16-roundtripped norm per row
#define OFF_CEN   (OFF_NQ + DIM)          // 16 centroids
#define OFF_BND   (OFF_CEN + 16)          // 15 interior boundaries (+pad)
#define SMEM_FLOATS (OFF_BND + 16)        // = 49952 floats = 199808 bytes

typedef unsigned long long u64;

__device__ __forceinline__ u64 pack2(float lo, float hi) {
    u64 r;
    asm("mov.b64 %0, {%1, %2};" : "=l"(r) : "f"(lo), "f"(hi));
    return r;
}
__device__ __forceinline__ void unpack2(u64 v, float& lo, float& hi) {
    asm("mov.b64 {%0, %1}, %2;" : "=f"(lo), "=f"(hi) : "l"(v));
}
// packed dual fp32 FMA (FFMA2) — 2x FFMA throughput on sm_103a, IEEE-identical per lane
__device__ __forceinline__ void ffma2(u64& d, u64 a, u64 b) {
    asm("fma.rn.f32x2 %0, %1, %2, %0;" : "+l"(d) : "l"(a), "l"(b));
}

__global__ void __launch_bounds__(NTHREADS, 1)
tq_kernel(const float* __restrict__ x, const float* __restrict__ Pi,
          const float* __restrict__ cen, const float* __restrict__ bnd,
          float* __restrict__ out)
{
    extern __shared__ float sm[];
    float* sPiT = sm + OFF_PIT;
    float* sPi  = sm + OFF_PI;
    float* sU   = sm + OFF_U;
    float* sInv = sm + OFF_INV;
    float* sNq  = sm + OFF_NQ;
    float* sCen = sm + OFF_CEN;
    float* sBnd = sm + OFF_BND;

    const int tid = threadIdx.x;
    const int tx  = tid & 15;        // 16 col-groups: cols {tx*4..+3} and {64+tx*4..+3}
    const int ty  = tid >> 4;        // 16 row-groups of 8 rows
    const size_t base = (size_t)blockIdx.x * (DIM * DIM);

    // ---- Pi row-major copy (coalesced gmem, conflict-free smem) ----
    #pragma unroll
    for (int it = 0; it < 16; ++it) {
        int q = tid + it * NTHREADS;                 // float4 index in [0,4096)
        float4 v = ((const float4*)Pi)[q];
        ((float4*)sPi)[q] = v;
    }
    // ---- Pi^T: lane -> consecutive j so smem stores are conflict-free ----
    {
        int j = tid & 127;
        int khalf = tid >> 7;                        // 0 or 1
        #pragma unroll
        for (int m = 0; m < 16; ++m) {
            int k4 = khalf * 16 + m;
            float4 v = *(const float4*)(Pi + j * DIM + k4 * 4);   // L2-served, strided ok
            int k = k4 * 4;
            sPiT[(k + 0) * DIM + j] = v.x;
            sPiT[(k + 1) * DIM + j] = v.y;
            sPiT[(k + 2) * DIM + j] = v.z;
            sPiT[(k + 3) * DIM + j] = v.w;
        }
    }
    // ---- x tile load (coalesced float4) ----
    #pragma unroll
    for (int it = 0; it < 16; ++it) {
        int q = tid + it * NTHREADS;                 // float4 index
        int r = q >> 5;
        int c = (q & 31) * 4;
        float4 v = *(const float4*)(x + base + (size_t)q * 4);
        *(float4*)(sU + r * UP + c) = v;
    }
    if (tid < 16) {
        sCen[tid] = cen[tid];
        sBnd[tid] = (tid < 15) ? bnd[tid + 1] : 3.0e38f;   // interior boundaries
    }
    __syncthreads();

    // ---- per-row norms: 2 threads/row ----
    {
        int r = tid >> 1, h = tid & 1;
        const float* p = sU + r * UP + h * 64;
        float s = 0.f;
        #pragma unroll
        for (int c = 0; c < 64; c += 4) {
            float4 v = *(const float4*)(p + c);
            s = fmaf(v.x, v.x, s); s = fmaf(v.y, v.y, s);
            s = fmaf(v.z, v.z, s); s = fmaf(v.w, v.w, s);
        }
        s += __shfl_xor_sync(0xffffffffu, s, 1);
        if (h == 0) {
            float n = __fsqrt_rn(s);
            sInv[r] = 1.0f / (n + 1e-8f);                   // fold unit-normalize post-matmul
            sNq[r]  = __half2float(__float2half(n));        // fp16 round-trip of norm
        }
    }
    float B[15];
    #pragma unroll
    for (int m = 0; m < 15; ++m) B[m] = sBnd[m];
    __syncthreads();

    // ---- matmul 1: rotated = x @ Pi^T  (then scale by inv-norm at quantize) ----
    u64 acc[8][4];
    #pragma unroll
    for (int i = 0; i < 8; ++i) {
        #pragma unroll
        for (int p = 0; p < 4; ++p) acc[i][p] = 0ull;
    }
    {
        const u64* pT = ((const u64*)sPiT) + tx * 2;
        const float* pu = sU + ty * 8 * UP;
        #pragma unroll 8
        for (int k = 0; k < DIM; ++k) {
            u64 b0 = pT[k * 64 + 0];
            u64 b1 = pT[k * 64 + 1];
            u64 b2 = pT[k * 64 + 32];
            u64 b3 = pT[k * 64 + 33];
            #pragma unroll
            for (int i = 0; i < 8; ++i) {
                float u = pu[i * UP + k];
                u64 uu = pack2(u, u);
                ffma2(acc[i][0], uu, b0);
                ffma2(acc[i][1], uu, b1);
                ffma2(acc[i][2], uu, b2);
                ffma2(acc[i][3], uu, b3);
            }
        }
    }

    // ---- quantize: searchsorted(left) over 15 boundaries -> centroid gather ----
    // result packed back into acc halves (keeps register pressure down)
    #pragma unroll
    for (int i = 0; i < 8; ++i) {
        float inv = sInv[ty * 8 + i];
        #pragma unroll
        for (int p = 0; p < 4; ++p) {
            float a, b;
            unpack2(acc[i][p], a, b);
            float r0 = a * inv, r1 = b * inv;
            int i0 = 0, i1 = 0;
            #pragma unroll
            for (int m = 0; m < 15; ++m) { i0 += (r0 > B[m]); i1 += (r1 > B[m]); }
            acc[i][p] = pack2(sCen[i0], sCen[i1]);
        }
    }
    __syncthreads();   // everyone finished reading sU (raw x) before overwrite
    #pragma unroll
    for (int i = 0; i < 8; ++i) {
        float v0, v1, v2, v3, v4, v5, v6, v7;
        unpack2(acc[i][0], v0, v1);
        unpack2(acc[i][1], v2, v3);
        unpack2(acc[i][2], v4, v5);
        unpack2(acc[i][3], v6, v7);
        float* row = sU + (ty * 8 + i) * UP;
        *(float4*)(row + tx * 4)      = make_float4(v0, v1, v2, v3);
        *(float4*)(row + 64 + tx * 4) = make_float4(v4, v5, v6, v7);
    }
    __syncthreads();

    // ---- matmul 2: recon = values @ Pi ----
    #pragma unroll
    for (int i = 0; i < 8; ++i) {
        #pragma unroll
        for (int p = 0; p < 4; ++p) acc[i][p] = 0ull;
    }
    {
        const u64* pP = ((const u64*)sPi) + tx * 2;
        const float* pv = sU + ty * 8 * UP;
        #pragma unroll 8
        for (int j = 0; j < DIM; ++j) {
            u64 b0 = pP[j * 64 + 0];
            u64 b1 = pP[j * 64 + 1];
            u64 b2 = pP[j * 64 + 32];
            u64 b3 = pP[j * 64 + 33];
            #pragma unroll
            for (int i = 0; i < 8; ++i) {
                float w = pv[i * UP + j];
                u64 ww = pack2(w, w);
                ffma2(acc[i][0], ww, b0);
                ffma2(acc[i][1], ww, b1);
                ffma2(acc[i][2], ww, b2);
                ffma2(acc[i][3], ww, b3);
            }
        }
    }

    // ---- epilogue: scale by fp16-roundtripped norm, coalesced float4 stores ----
    #pragma unroll
    for (int i = 0; i < 8; ++i) {
        float nq = sNq[ty * 8 + i];
        float o0, o1, o2, o3, o4, o5, o6, o7;
        unpack2(acc[i][0], o0, o1);
        unpack2(acc[i][1], o2, o3);
        unpack2(acc[i][2], o4, o5);
        unpack2(acc[i][3], o6, o7);
        float* orow = out + base + (size_t)(ty * 8 + i) * DIM;
        *(float4*)(orow + tx * 4)      = make_float4(o0 * nq, o1 * nq, o2 * nq, o3 * nq);
        *(float4*)(orow + 64 + tx * 4) = make_float4(o4 * nq, o5 * nq, o6 * nq, o7 * nq);
    }
}

extern "C" void kernel_launch(void* const* d_in, const int* in_sizes, int n_in,
                              void* d_out, int out_size)
{
    const float* x   = (const float*)d_in[0];
    const float* Pi  = (const float*)d_in[1];
    const float* cen = (const float*)d_in[2];
    const float* bnd = (const float*)d_in[3];
    float* out = (float*)d_out;

    int rows = in_sizes[0] / DIM;       // 262144
    int grid = rows / DIM;              // 2048 blocks of 128 rows

    size_t smem = SMEM_FLOATS * sizeof(float);   // 199808 B
    cudaFuncSetAttribute(tq_kernel, cudaFuncAttributeMaxDynamicSharedMemorySize, (int)smem);
    tq_kernel<<<grid, NTHREADS, smem>>>(x, Pi, cen, bnd, out);
}

// round 7
// speedup vs baseline: 1.0028x; 1.0028x over previous
#include <cuda_runtime.h>
#include <cuda_fp16.h>

#define DIM       128
#define UP        132          // padded sU row stride (floats), multiple of 4 for float4
#define NTHREADS  256

// shared memory layout (float offsets)
#define OFF_PIT   0                       // Pi^T  [k][j], 128x128
#define OFF_PI    (DIM * DIM)             // Pi    [j][k], 128x128
#define OFF_U     (2 * DIM * DIM)         // x tile / quantized values, 128xUP
#define OFF_INV   (OFF_U + DIM * UP)      // 1/(norm+1e-8) per row
#define OFF_NQ    (OFF_INV + DIM)         // fp16-roundtripped norm per row
#define OFF_CEN   (OFF_NQ + DIM)          // 16 centroids
#define OFF_BND   (OFF_CEN + 16)          // 15 interior boundaries (+pad)
#define SMEM_FLOATS (OFF_BND + 16)        // = 49952 floats = 199808 bytes

typedef unsigned long long u64;

__device__ __forceinline__ u64 pack2(float lo, float hi) {
    u64 r;
    asm("mov.b64 %0, {%1, %2};" : "=l"(r) : "f"(lo), "f"(hi));
    return r;
}
__device__ __forceinline__ void unpack2(u64 v, float& lo, float& hi) {
    asm("mov.b64 {%0, %1}, %2;" : "=f"(lo), "=f"(hi) : "l"(v));
}
// packed dual fp32 FMA (FFMA2) — 2x FFMA throughput on sm_103a, IEEE-identical per lane
__device__ __forceinline__ void ffma2(u64& d, u64 a, u64 b) {
    asm("fma.rn.f32x2 %0, %1, %2, %0;" : "+l"(d) : "l"(a), "l"(b));
}

__global__ void __launch_bounds__(NTHREADS, 1)
tq_kernel(const float* __restrict__ x, const float* __restrict__ Pi,
          const float* __restrict__ cen, const float* __restrict__ bnd,
          float* __restrict__ out)
{
    extern __shared__ float sm[];
    float* sPiT = sm + OFF_PIT;
    float* sPi  = sm + OFF_PI;
    float* sU   = sm + OFF_U;
    float* sInv = sm + OFF_INV;
    float* sNq  = sm + OFF_NQ;
    float* sCen = sm + OFF_CEN;
    float* sBnd = sm + OFF_BND;

    const int tid = threadIdx.x;
    const int tx  = tid & 15;        // 16 col-groups: cols {tx*4..+3} and {64+tx*4..+3}
    const int ty  = tid >> 4;        // 16 row-groups of 8 rows
    const size_t base = (size_t)blockIdx.x * (DIM * DIM);

    // ---- Pi row-major copy (coalesced gmem, conflict-free smem) ----
    #pragma unroll
    for (int it = 0; it < 16; ++it) {
        int q = tid + it * NTHREADS;                 // float4 index in [0,4096)
        float4 v = ((const float4*)Pi)[q];
        ((float4*)sPi)[q] = v;
    }
    // ---- Pi^T: lane -> consecutive j so smem stores are conflict-free ----
    {
        int j = tid & 127;
        int khalf = tid >> 7;                        // 0 or 1
        #pragma unroll
        for (int m = 0; m < 16; ++m) {
            int k4 = khalf * 16 + m;
            float4 v = *(const float4*)(Pi + j * DIM + k4 * 4);   // L2-served, strided ok
            int k = k4 * 4;
            sPiT[(k + 0) * DIM + j] = v.x;
            sPiT[(k + 1) * DIM + j] = v.y;
            sPiT[(k + 2) * DIM + j] = v.z;
            sPiT[(k + 3) * DIM + j] = v.w;
        }
    }
    // ---- x tile load (coalesced float4) ----
    #pragma unroll
    for (int it = 0; it < 16; ++it) {
        int q = tid + it * NTHREADS;                 // float4 index
        int r = q >> 5;
        int c = (q & 31) * 4;
        float4 v = *(const float4*)(x + base + (size_t)q * 4);
        *(float4*)(sU + r * UP + c) = v;
    }
    if (tid < 16) {
        sCen[tid] = cen[tid];
        sBnd[tid] = (tid < 15) ? bnd[tid + 1] : 3.0e38f;   // interior boundaries
    }
    __syncthreads();

    // ---- per-row norms: 2 threads/row ----
    {
        int r = tid >> 1, h = tid & 1;
        const float* p = sU + r * UP + h * 64;
        float s = 0.f;
        #pragma unroll
        for (int c = 0; c < 64; c += 4) {
            float4 v = *(const float4*)(p + c);
            s = fmaf(v.x, v.x, s); s = fmaf(v.y, v.y, s);
            s = fmaf(v.z, v.z, s); s = fmaf(v.w, v.w, s);
        }
        s += __shfl_xor_sync(0xffffffffu, s, 1);
        if (h == 0) {
            float n = __fsqrt_rn(s);
            sInv[r] = 1.0f / (n + 1e-8f);                   // fold unit-normalize post-matmul
            sNq[r]  = __half2float(__float2half(n));        // fp16 round-trip of norm
        }
    }
    float B[15];
    #pragma unroll
    for (int m = 0; m < 15; ++m) B[m] = sBnd[m];
    __syncthreads();

    // ---- matmul 1: rotated = x @ Pi^T  (then scale by inv-norm at quantize) ----
    u64 acc[8][4];
    #pragma unroll
    for (int i = 0; i < 8; ++i) {
        #pragma unroll
        for (int p = 0; p < 4; ++p) acc[i][p] = 0ull;
    }
    {
        const u64* pT = ((const u64*)sPiT) + tx * 2;
        const float* pu = sU + ty * 8 * UP;
        #pragma unroll 8
        for (int k = 0; k < DIM; ++k) {
            u64 b0 = pT[k * 64 + 0];
            u64 b1 = pT[k * 64 + 1];
            u64 b2 = pT[k * 64 + 32];
            u64 b3 = pT[k * 64 + 33];
            #pragma unroll
            for (int i = 0; i < 8; ++i) {
                float u = pu[i * UP + k];
                u64 uu = pack2(u, u);
                ffma2(acc[i][0], uu, b0);
                ffma2(acc[i][1], uu, b1);
                ffma2(acc[i][2], uu, b2);
                ffma2(acc[i][3], uu, b3);
            }
        }
    }

    // ---- quantize: searchsorted(left) over 15 boundaries -> centroid gather ----
    // result packed back into acc halves (keeps register pressure down)
    #pragma unroll
    for (int i = 0; i < 8; ++i) {
        float inv = sInv[ty * 8 + i];
        #pragma unroll
        for (int p = 0; p < 4; ++p) {
            float a, b;
            unpack2(acc[i][p], a, b);
            float r0 = a * inv, r1 = b * inv;
            int i0 = 0, i1 = 0;
            #pragma unroll
            for (int m = 0; m < 15; ++m) { i0 += (r0 > B[m]); i1 += (r1 > B[m]); }
            acc[i][p] = pack2(sCen[i0], sCen[i1]);
        }
    }
    __syncthreads();   // everyone finished reading sU (raw x) before overwrite
    #pragma unroll
    for (int i = 0; i < 8; ++i) {
        float v0, v1, v2, v3, v4, v5, v6, v7;
        unpack2(acc[i][0], v0, v1);
        unpack2(acc[i][1], v2, v3);
        unpack2(acc[i][2], v4, v5);
        unpack2(acc[i][3], v6, v7);
        float* row = sU + (ty * 8 + i) * UP;
        *(float4*)(row + tx * 4)      = make_float4(v0, v1, v2, v3);
        *(float4*)(row + 64 + tx * 4) = make_float4(v4, v5, v6, v7);
    }
    __syncthreads();

    // ---- matmul 2: recon = values @ Pi ----
    #pragma unroll
    for (int i = 0; i < 8; ++i) {
        #pragma unroll
        for (int p = 0; p < 4; ++p) acc[i][p] = 0ull;
    }
    {
        const u64* pP = ((const u64*)sPi) + tx * 2;
        const float* pv = sU + ty * 8 * UP;
        #pragma unroll 8
        for (int j = 0; j < DIM; ++j) {
            u64 b0 = pP[j * 64 + 0];
            u64 b1 = pP[j * 64 + 1];
            u64 b2 = pP[j * 64 + 32];
            u64 b3 = pP[j * 64 + 33];
            #pragma unroll
            for (int i = 0; i < 8; ++i) {
                float w = pv[i * UP + j];
                u64 ww = pack2(w, w);
                ffma2(acc[i][0], ww, b0);
                ffma2(acc[i][1], ww, b1);
                ffma2(acc[i][2], ww, b2);
                ffma2(acc[i][3], ww, b3);
            }
        }
    }

    // ---- epilogue: scale by fp16-roundtripped norm, coalesced float4 stores ----
    #pragma unroll
    for (int i = 0; i < 8; ++i) {
        float nq = sNq[ty * 8 + i];
        float o0, o1, o2, o3, o4, o5, o6, o7;
        unpack2(acc[i][0], o0, o1);
        unpack2(acc[i][1], o2, o3);
        unpack2(acc[i][2], o4, o5);
        unpack2(acc[i][3], o6, o7);
        float* orow = out + base + (size_t)(ty * 8 + i) * DIM;
        *(float4*)(orow + tx * 4)      = make_float4(o0 * nq, o1 * nq, o2 * nq, o3 * nq);
        *(float4*)(orow + 64 + tx * 4) = make_float4(o4 * nq, o5 * nq, o6 * nq, o7 * nq);
    }
}

extern "C" void kernel_launch(void* const* d_in, const int* in_sizes, int n_in,
                              void* d_out, int out_size)
{
    const float* x   = (const float*)d_in[0];
    const float* Pi  = (const float*)d_in[1];
    const float* cen = (const float*)d_in[2];
    const float* bnd = (const float*)d_in[3];
    float* out = (float*)d_out;

    int rows = in_sizes[0] / DIM;       // 262144
    int grid = rows / DIM;              // 2048 blocks of 128 rows

    size_t smem = SMEM_FLOATS * sizeof(float);   // 199808 B
    cudaFuncSetAttribute(tq_kernel, cudaFuncAttributeMaxDynamicSharedMemorySize, (int)smem);
    tq_kernel<<<grid, NTHREADS, smem>>>(x, Pi, cen, bnd, out);
}

// round 13
// speedup vs baseline: 1.9786x; 1.9732x over previous
#include <cuda_runtime.h>
#include <cuda_fp16.h>
#include <cstdint>

typedef unsigned int u32;
typedef unsigned long long u64;

#define NT   256
#define PH   136                    // pitch in halves (272B rows -> conflict-free ldmatrix)
#define TILEB (128 * PH * 2)        // 34816 B per fp16 tile

// smem byte offsets
#define SM_AH   0                   // A hi (x split, later quantized values hi)
#define SM_AL   (TILEB)             // A lo
#define SM_B1H  (2*TILEB)           // GEMM1 B hi: Pi[n][k]*256
#define SM_B1L  (3*TILEB)
#define SM_B2H  (4*TILEB)           // GEMM2 B hi: Pi^T[j][n]*256
#define SM_B2L  (5*TILEB)
#define SM_RED  (6*TILEB)           // 128 floats: per-row omul = half_rt(norm)*2^-17
#define SM_LUT  (SM_RED + 512)      // 128 x uint2 {boundary_bits, base}
#define SM_CEN  (SM_LUT + 1024)     // 16 x u32 packed (hi16|lo16) centroids*512
#define SM_BNDT (SM_CEN + 64)       // 16 floats scaled boundaries (prologue only)
#define SM_TOT  (SM_BNDT + 64)      // 210,560 B

__device__ __forceinline__ u32 s2u(const void* p) {
    u32 a; asm("{ .reg .u64 t; cvta.to.shared.u64 t, %1; cvt.u32.u64 %0, t; }" : "=r"(a) : "l"(p));
    return a;
}
__device__ __forceinline__ void ldmx4(u32 a, u32* r) {
    asm volatile("ldmatrix.sync.aligned.m8n8.x4.shared.b16 {%0,%1,%2,%3}, [%4];"
        : "=r"(r[0]), "=r"(r[1]), "=r"(r[2]), "=r"(r[3]) : "r"(a));
}
__device__ __forceinline__ void mma16816(float* c, const u32* a, const u32* b) {
    asm volatile("mma.sync.aligned.m16n8k16.row.col.f32.f16.f16.f32 "
        "{%0,%1,%2,%3}, {%4,%5,%6,%7}, {%8,%9}, {%0,%1,%2,%3};"
        : "+f"(c[0]), "+f"(c[1]), "+f"(c[2]), "+f"(c[3])
        : "r"(a[0]), "r"(a[1]), "r"(a[2]), "r"(a[3]), "r"(b[0]), "r"(b[1]));
}

// 3-term split GEMM: acc += Ah@Bh + Al@Bh + Ah@Bl   (K=128, 8 ksteps)
__device__ __forceinline__ void gemm3(float acc[2][8][4],
                                      u32 bah, u32 bal, u32 bbh, u32 bbl,
                                      u32 pA0, u32 pA1, const u32* pB)
{
    #pragma unroll
    for (int kc = 0; kc < 8; ++kc) {
        u32 ko = (u32)kc * 32;               // 16 halves per kstep = 32B
        u32 ah0[4], ah1[4], al0[4], al1[4], bh[4][4], bl[4][4];
        ldmx4(bah + pA0 + ko, ah0);
        ldmx4(bah + pA1 + ko, ah1);
        ldmx4(bal + pA0 + ko, al0);
        ldmx4(bal + pA1 + ko, al1);
        #pragma unroll
        for (int pi = 0; pi < 4; ++pi) {
            ldmx4(bbh + pB[pi] + ko, bh[pi]);
            ldmx4(bbl + pB[pi] + ko, bl[pi]);
        }
        #pragma unroll
        for (int pi = 0; pi < 4; ++pi) {
            mma16816(acc[0][2*pi],   ah0, &bh[pi][0]);
            mma16816(acc[0][2*pi+1], ah0, &bh[pi][2]);
            mma16816(acc[1][2*pi],   ah1, &bh[pi][0]);
            mma16816(acc[1][2*pi+1], ah1, &bh[pi][2]);
            mma16816(acc[0][2*pi],   al0, &bh[pi][0]);
            mma16816(acc[0][2*pi+1], al0, &bh[pi][2]);
            mma16816(acc[1][2*pi],   al1, &bh[pi][0]);
            mma16816(acc[1][2*pi+1], al1, &bh[pi][2]);
            mma16816(acc[0][2*pi],   ah0, &bl[pi][0]);
            mma16816(acc[0][2*pi+1], ah0, &bl[pi][2]);
            mma16816(acc[1][2*pi],   ah1, &bl[pi][0]);
            mma16816(acc[1][2*pi+1], ah1, &bl[pi][2]);
        }
    }
}

__global__ void __launch_bounds__(NT, 1)
tq12_kernel(const float* __restrict__ x, const float* __restrict__ Pi,
            const float* __restrict__ cen, const float* __restrict__ bnd,
            float* __restrict__ out, int ntiles)
{
    extern __shared__ __align__(16) char smem[];
    const u32 sb   = s2u(smem);
    const int tid  = threadIdx.x;
    const int warp = tid >> 5;
    const int lane = tid & 31;
    float* redf = (float*)(smem + SM_RED);
    float* bndT = (float*)(smem + SM_BNDT);
    const uint2* lut = (const uint2*)(smem + SM_LUT);

    // ---------------- prologue ----------------
    if (tid < 16) {
        bndT[tid] = (tid < 15) ? bnd[tid + 1] * 131072.0f : __int_as_float(0x7f800000);
        float c = cen[tid] * 512.0f;
        __half h = __float2half_rn(c);
        __half l = __float2half_rn(c - __half2float(h));
        *(u32*)(smem + SM_CEN + tid * 4) =
            (u32)__half_as_ushort(h) | ((u32)__half_as_ushort(l) << 16);
    }
    // B tiles: B1[row=n][col=k] = Pi[n][k]*256 ; B2[row=j][col=n] = Pi[n][j]*256, hi/lo
    for (int idx = tid; idx < 16384; idx += NT) {
        int row = idx >> 7, col = idx & 127;
        u32 o = (u32)(row * PH + col) * 2;
        float a = Pi[(row << 7) + col] * 256.0f;
        __half ah = __float2half_rn(a);
        *(__half*)(smem + SM_B1H + o) = ah;
        *(__half*)(smem + SM_B1L + o) = __float2half_rn(a - __half2float(ah));
        float b = Pi[(col << 7) + row] * 256.0f;
        __half bh = __float2half_rn(b);
        *(__half*)(smem + SM_B2H + o) = bh;
        *(__half*)(smem + SM_B2L + o) = __float2half_rn(b - __half2float(bh));
    }
    __syncthreads();

    const float Lb = bndT[0], Hb = bndT[14];
    const float sc = 127.0f / (Hb - Lb);
    const float nLbsc = -Lb * sc;
    if (tid < 128) {   // LUT: at most one boundary per cell (min gap = 6.3 cells)
        float eps = 0.5f * (Hb - Lb) * (1.0f / 127.0f);
        float edge = Lb + (float)tid * ((Hb - Lb) * (1.0f / 127.0f)) - eps;
        int base = 0;
        #pragma unroll
        for (int m = 0; m < 15; ++m) base += (bndT[m] < edge);
        uint2 e; e.x = __float_as_uint(bndT[base]); e.y = (u32)base;
        *(uint2*)(smem + SM_LUT + tid * 8) = e;
    }
    __syncthreads();
    const u32 cenw = *(const u32*)(smem + SM_CEN + ((lane & 15) << 2));

    // per-lane ldmatrix address patterns (bytes)
    const int Rw = (warp >> 1) * 32;          // warp output rows
    const int Cw = (warp & 1) * 64;           // warp output cols
    const int g  = lane >> 3;
    const u32 pA0 = (u32)(((Rw + (lane & 7) + (g & 1) * 8) * PH + (lane >> 4) * 8) * 2);
    const u32 pA1 = pA0 + (u32)(16 * PH * 2);
    u32 pB[4];
    #pragma unroll
    for (int pi = 0; pi < 4; ++pi)
        pB[pi] = (u32)(((Cw + pi * 16 + ((g >> 1) & 1) * 8 + (lane & 7)) * PH + (g & 1) * 8) * 2);

    // ---------------- per-tile loop ----------------
    for (int t = blockIdx.x; t < ntiles; t += gridDim.x) {
        // load tile: warp w iter j covers row (w + 8j), lane -> float4 col
        const float4* src = (const float4*)x + ((size_t)t << 12);
        float4 pf[16];
        #pragma unroll
        for (int j = 0; j < 16; ++j) pf[j] = src[tid + (j << 8)];

        // norms + hi/lo split -> sAh/sAl
        #pragma unroll
        for (int j = 0; j < 16; ++j) {
            int row = warp + 8 * j;
            float4 v = pf[j];
            float ss = v.x * v.x;
            ss = fmaf(v.y, v.y, ss); ss = fmaf(v.z, v.z, ss); ss = fmaf(v.w, v.w, ss);
            #pragma unroll
            for (int o = 16; o > 0; o >>= 1) ss += __shfl_xor_sync(0xffffffffu, ss, o);
            float n = __fsqrt_rn(ss);
            float s512 = 512.0f / (n + 1e-8f);
            if (lane == 0)
                redf[row] = __half2float(__float2half_rn(n)) * 7.62939453125e-06f; // nq*2^-17
            float u0 = v.x * s512, u1 = v.y * s512, u2 = v.z * s512, u3 = v.w * s512;
            __half h0 = __float2half_rn(u0), h1 = __float2half_rn(u1);
            __half h2 = __float2half_rn(u2), h3 = __float2half_rn(u3);
            uint2 hw, lw;
            hw.x = (u32)__half_as_ushort(h0) | ((u32)__half_as_ushort(h1) << 16);
            hw.y = (u32)__half_as_ushort(h2) | ((u32)__half_as_ushort(h3) << 16);
            __half l0 = __float2half_rn(u0 - __half2float(h0));
            __half l1 = __float2half_rn(u1 - __half2float(h1));
            __half l2 = __float2half_rn(u2 - __half2float(h2));
            __half l3 = __float2half_rn(u3 - __half2float(h3));
            lw.x = (u32)__half_as_ushort(l0) | ((u32)__half_as_ushort(l1) << 16);
            lw.y = (u32)__half_as_ushort(l2) | ((u32)__half_as_ushort(l3) << 16);
            u32 o = (u32)(row * PH + lane * 4) * 2;
            *(uint2*)(smem + SM_AH + o) = hw;
            *(uint2*)(smem + SM_AL + o) = lw;
        }
        __syncthreads();

        // GEMM1: rotated*2^17
        float acc[2][8][4];
        #pragma unroll
        for (int mi = 0; mi < 2; ++mi)
            #pragma unroll
            for (int ni = 0; ni < 8; ++ni)
                #pragma unroll
                for (int p = 0; p < 4; ++p) acc[mi][ni][p] = 0.0f;
        gemm3(acc, sb + SM_AH, sb + SM_AL, sb + SM_B1H, sb + SM_B1L, pA0, pA1, pB);
        __syncthreads();   // all warps done reading sA before overwrite

        // quantize accumulators -> values*512 hi/lo back into sAh/sAl
        #pragma unroll
        for (int mi = 0; mi < 2; ++mi) {
            #pragma unroll
            for (int ni = 0; ni < 8; ++ni) {
                const float* c = acc[mi][ni];
                int row0 = Rw + mi * 16 + (lane >> 2);
                int col  = Cw + ni * 8 + (lane & 3) * 2;
                u32 w[4];
                #pragma unroll
                for (int p = 0; p < 4; ++p) {
                    float v = c[p];
                    int cell = (int)fminf(fmaxf(fmaf(v, sc, nLbsc), 0.0f), 127.0f);
                    uint2 e = lut[cell];
                    int idx = (int)e.y + (v > __uint_as_float(e.x));
                    w[p] = __shfl_sync(0xffffffffu, cenw, idx);
                }
                u32 o0 = (u32)(row0 * PH + col) * 2;
                u32 o1 = o0 + (u32)(8 * PH * 2);
                *(u32*)(smem + SM_AH + o0) = __byte_perm(w[0], w[1], 0x5410);
                *(u32*)(smem + SM_AL + o0) = __byte_perm(w[0], w[1], 0x7632);
                *(u32*)(smem + SM_AH + o1) = __byte_perm(w[2], w[3], 0x5410);
                *(u32*)(smem + SM_AL + o1) = __byte_perm(w[2], w[3], 0x7632);
            }
        }
        __syncthreads();

        // GEMM2: recon*2^17
        #pragma unroll
        for (int mi = 0; mi < 2; ++mi)
            #pragma unroll
            for (int ni = 0; ni < 8; ++ni)
                #pragma unroll
                for (int p = 0; p < 4; ++p) acc[mi][ni][p] = 0.0f;
        gemm3(acc, sb + SM_AH, sb + SM_AL, sb + SM_B2H, sb + SM_B2L, pA0, pA1, pB);

        // epilogue: scale by nq*2^-17, direct gmem stores (float2 pairs)
        float* og = out + ((size_t)t << 14);
        #pragma unroll
        for (int mi = 0; mi < 2; ++mi) {
            #pragma unroll
            for (int ni = 0; ni < 8; ++ni) {
                const float* c = acc[mi][ni];
                int row0 = Rw + mi * 16 + (lane >> 2);
                int col  = Cw + ni * 8 + (lane & 3) * 2;
                float om0 = redf[row0];
                float om1 = redf[row0 + 8];
                *(float2*)(og + (size_t)row0 * 128 + col) =
                    make_float2(c[0] * om0, c[1] * om0);
                *(float2*)(og + (size_t)(row0 + 8) * 128 + col) =
                    make_float2(c[2] * om1, c[3] * om1);
            }
        }
        __syncthreads();   // protect sA/redf before next tile's writes
    }
}

extern "C" void kernel_launch(void* const* d_in, const int* in_sizes, int n_in,
                              void* d_out, int out_size)
{
    const float* x   = (const float*)d_in[0];
    const float* Pi  = (const float*)d_in[1];
    const float* cen = (const float*)d_in[2];
    const float* bnd = (const float*)d_in[3];
    float* out = (float*)d_out;

    int ntiles = in_sizes[0] / (128 * 128);      // 2048
    static int nsm = 0;
    if (nsm == 0) {       // populated on the uncaptured correctness call
        if (cudaDeviceGetAttribute(&nsm, cudaDevAttrMultiProcessorCount, 0) != cudaSuccess || nsm <= 0)
            nsm = 148;
    }
    int grid = nsm < ntiles ? nsm : ntiles;

    cudaFuncSetAttribute(tq12_kernel, cudaFuncAttributeMaxDynamicSharedMemorySize, SM_TOT);
    tq12_kernel<<<grid, NT, SM_TOT>>>(x, Pi, cen, bnd, out, ntiles);
}

// round 14
// speedup vs baseline: 2.1778x; 1.1006x over previous
#include <cuda_runtime.h>
#include <cuda_fp16.h>
#include <cstdint>

typedef unsigned int u32;
typedef unsigned long long u64;

#define NT   512
#define PH   136                    // pitch in halves (272B rows -> conflict-free ldmatrix, both normal & trans)
#define TILEB (128 * PH * 2)        // 34816 B per fp16 tile

// smem byte offsets
#define SM_A    0                   // 4 A tiles: group0 {hi,lo}, group1 {hi,lo}
#define SM_B1H  (4*TILEB)           // B hi: Pi[n][k]*256   (GEMM1 normal, GEMM2 via ldmatrix.trans)
#define SM_B1L  (5*TILEB)
#define SM_RED  (6*TILEB)           // 2 x 128 floats: per-row omul = half_rt(norm)*2^-17
#define SM_LUT  (SM_RED + 1024)     // 128 x uint2 {boundary_bits, base}
#define SM_CEN  (SM_LUT + 1024)     // 16 x u32 packed (hi16|lo16) centroids*512
#define SM_BNDT (SM_CEN + 64)       // 16 floats scaled boundaries (prologue only)
#define SM_TOT  (SM_BNDT + 64)      // 211,072 B

__device__ __forceinline__ u32 s2u(const void* p) {
    u32 a; asm("{ .reg .u64 t; cvta.to.shared.u64 t, %1; cvt.u32.u64 %0, t; }" : "=r"(a) : "l"(p));
    return a;
}
__device__ __forceinline__ void ldmx4(u32 a, u32* r) {
    asm volatile("ldmatrix.sync.aligned.m8n8.x4.shared.b16 {%0,%1,%2,%3}, [%4];"
        : "=r"(r[0]), "=r"(r[1]), "=r"(r[2]), "=r"(r[3]) : "r"(a));
}
__device__ __forceinline__ void ldmx4t(u32 a, u32* r) {
    asm volatile("ldmatrix.sync.aligned.m8n8.x4.trans.shared.b16 {%0,%1,%2,%3}, [%4];"
        : "=r"(r[0]), "=r"(r[1]), "=r"(r[2]), "=r"(r[3]) : "r"(a));
}
__device__ __forceinline__ void mma16816(float* c, const u32* a, const u32* b) {
    asm volatile("mma.sync.aligned.m16n8k16.row.col.f32.f16.f16.f32 "
        "{%0,%1,%2,%3}, {%4,%5,%6,%7}, {%8,%9}, {%0,%1,%2,%3};"
        : "+f"(c[0]), "+f"(c[1]), "+f"(c[2]), "+f"(c[3])
        : "r"(a[0]), "r"(a[1]), "r"(a[2]), "r"(a[3]), "r"(b[0]), "r"(b[1]));
}
__device__ __forceinline__ void barg(int id) {
    asm volatile("bar.sync %0, %1;" :: "r"(id), "r"(256) : "memory");
}

// 3-term split GEMM: acc += Ah@Bh + Al@Bh + Ah@Bl   (K=128, 8 ksteps)
// TR=0: B read normal (kstep advances along row, 32B). TR=1: B read transposed
// via ldmatrix.trans (kstep advances 16 rows = 32*PH bytes).
template<int TR>
__device__ __forceinline__ void gemm3(float acc[2][8][4],
                                      u32 bah, u32 bal, u32 bbh, u32 bbl,
                                      u32 pA0, u32 pA1, const u32* pB)
{
    #pragma unroll
    for (int kc = 0; kc < 8; ++kc) {
        u32 koA = (u32)kc * 32;
        u32 koB = TR ? (u32)kc * (u32)(32 * PH) : (u32)kc * 32;
        u32 ah0[4], ah1[4], al0[4], al1[4];
        ldmx4(bah + pA0 + koA, ah0);
        ldmx4(bah + pA1 + koA, ah1);
        ldmx4(bal + pA0 + koA, al0);
        ldmx4(bal + pA1 + koA, al1);
        #pragma unroll
        for (int pi = 0; pi < 4; ++pi) {
            u32 bh[4], bl[4];
            if (TR) { ldmx4t(bbh + pB[pi] + koB, bh); ldmx4t(bbl + pB[pi] + koB, bl); }
            else    { ldmx4 (bbh + pB[pi] + koB, bh); ldmx4 (bbl + pB[pi] + koB, bl); }
            mma16816(acc[0][2*pi],   ah0, &bh[0]);
            mma16816(acc[0][2*pi+1], ah0, &bh[2]);
            mma16816(acc[1][2*pi],   ah1, &bh[0]);
            mma16816(acc[1][2*pi+1], ah1, &bh[2]);
            mma16816(acc[0][2*pi],   al0, &bh[0]);
            mma16816(acc[0][2*pi+1], al0, &bh[2]);
            mma16816(acc[1][2*pi],   al1, &bh[0]);
            mma16816(acc[1][2*pi+1], al1, &bh[2]);
            mma16816(acc[0][2*pi],   ah0, &bl[0]);
            mma16816(acc[0][2*pi+1], ah0, &bl[2]);
            mma16816(acc[1][2*pi],   ah1, &bl[0]);
            mma16816(acc[1][2*pi+1], ah1, &bl[2]);
        }
    }
}

__global__ void __launch_bounds__(NT, 1)
tq14_kernel(const float* __restrict__ x, const float* __restrict__ Pi,
            const float* __restrict__ cen, const float* __restrict__ bnd,
            float* __restrict__ out, int ntiles)
{
    extern __shared__ __align__(16) char smem[];
    const u32 sb   = s2u(smem);
    const int tid  = threadIdx.x;
    const int warp = tid >> 5;
    const int lane = tid & 31;
    const int gw   = warp >> 3;          // warp-group 0/1 (independent tile streams)
    const int wg   = warp & 7;           // warp within group
    float* bndT = (float*)(smem + SM_BNDT);
    const uint2* lut = (const uint2*)(smem + SM_LUT);
    float* redf = (float*)(smem + SM_RED) + gw * 128;

    // ---------------- prologue (all 512 threads) ----------------
    if (tid < 16) {
        bndT[tid] = (tid < 15) ? bnd[tid + 1] * 131072.0f : __int_as_float(0x7f800000);
        float c = cen[tid] * 512.0f;
        __half h = __float2half_rn(c);
        __half l = __float2half_rn(c - __half2float(h));
        *(u32*)(smem + SM_CEN + tid * 4) =
            (u32)__half_as_ushort(h) | ((u32)__half_as_ushort(l) << 16);
    }
    // B tile: B1[row=n][col=k] = Pi[n][k]*256, hi/lo (GEMM2 reads it transposed)
    for (int idx = tid; idx < 16384; idx += NT) {
        int row = idx >> 7, col = idx & 127;
        u32 o = (u32)(row * PH + col) * 2;
        float a = Pi[(row << 7) + col] * 256.0f;
        __half ah = __float2half_rn(a);
        *(__half*)(smem + SM_B1H + o) = ah;
        *(__half*)(smem + SM_B1L + o) = __float2half_rn(a - __half2float(ah));
    }
    __syncthreads();

    const float Lb = bndT[0], Hb = bndT[14];
    const float sc = 127.0f / (Hb - Lb);
    const float nLbsc = -Lb * sc;
    if (tid < 128) {   // LUT: at most one boundary per cell (min gap = 6.3 cells)
        float eps = 0.5f * (Hb - Lb) * (1.0f / 127.0f);
        float edge = Lb + (float)tid * ((Hb - Lb) * (1.0f / 127.0f)) - eps;
        int base = 0;
        #pragma unroll
        for (int m = 0; m < 15; ++m) base += (bndT[m] < edge);
        uint2 e; e.x = __float_as_uint(bndT[base]); e.y = (u32)base;
        *(uint2*)(smem + SM_LUT + tid * 8) = e;
    }
    __syncthreads();
    const u32 cenw = *(const u32*)(smem + SM_CEN + ((lane & 15) << 2));

    // group A-tile bases
    const u32 bAH = sb + (u32)SM_A + (u32)gw * (2 * TILEB);
    const u32 bAL = bAH + TILEB;
    char* cAH = smem + SM_A + gw * (2 * TILEB);
    char* cAL = cAH + TILEB;

    // per-lane ldmatrix address patterns (bytes)
    const int Rw = (wg >> 1) * 32;          // warp output rows
    const int Cw = (wg & 1) * 64;           // warp output cols
    const int g  = lane >> 3;
    const u32 pA0 = (u32)(((Rw + (lane & 7) + (g & 1) * 8) * PH + (lane >> 4) * 8) * 2);
    const u32 pA1 = pA0 + (u32)(16 * PH * 2);
    u32 pB1[4], pB2[4];
    #pragma unroll
    for (int pi = 0; pi < 4; ++pi) {
        // GEMM1 (normal): tile rows = n, within-row offset = k
        pB1[pi] = (u32)(((Cw + pi * 16 + ((g >> 1) & 1) * 8 + (lane & 7)) * PH + (g & 1) * 8) * 2);
        // GEMM2 (trans): source rows = k' (n-dim), cols = output j
        pB2[pi] = (u32)((((g & 1) * 8 + (lane & 7)) * PH + Cw + pi * 16 + ((g >> 1) & 1) * 8) * 2);
    }
    const int barid = 1 + gw;

    // ---------------- per-tile loop: group gw owns stream t ----------------
    for (int t = blockIdx.x * 2 + gw; t < ntiles; t += gridDim.x * 2) {
        // load + norms + hi/lo split (row-wise, depth-2 pipelined; row = wg + 8j)
        const float4* src = (const float4*)x + ((size_t)t << 12);
        float4 vc = src[wg * 32 + lane];
        #pragma unroll
        for (int j = 0; j < 16; ++j) {
            float4 v = vc;
            if (j < 15) vc = src[(wg + 8 * (j + 1)) * 32 + lane];
            int row = wg + 8 * j;
            float ss = v.x * v.x;
            ss = fmaf(v.y, v.y, ss); ss = fmaf(v.z, v.z, ss); ss = fmaf(v.w, v.w, ss);
            #pragma unroll
            for (int o = 16; o > 0; o >>= 1) ss += __shfl_xor_sync(0xffffffffu, ss, o);
            float n = __fsqrt_rn(ss);
            float s512 = 512.0f / (n + 1e-8f);
            if (lane == 0)
                redf[row] = __half2float(__float2half_rn(n)) * 7.62939453125e-06f; // nq*2^-17
            float u0 = v.x * s512, u1 = v.y * s512, u2 = v.z * s512, u3 = v.w * s512;
            __half h0 = __float2half_rn(u0), h1 = __float2half_rn(u1);
            __half h2 = __float2half_rn(u2), h3 = __float2half_rn(u3);
            uint2 hw, lw;
            hw.x = (u32)__half_as_ushort(h0) | ((u32)__half_as_ushort(h1) << 16);
            hw.y = (u32)__half_as_ushort(h2) | ((u32)__half_as_ushort(h3) << 16);
            __half l0 = __float2half_rn(u0 - __half2float(h0));
            __half l1 = __float2half_rn(u1 - __half2float(h1));
            __half l2 = __float2half_rn(u2 - __half2float(h2));
            __half l3 = __float2half_rn(u3 - __half2float(h3));
            lw.x = (u32)__half_as_ushort(l0) | ((u32)__half_as_ushort(l1) << 16);
            lw.y = (u32)__half_as_ushort(l2) | ((u32)__half_as_ushort(l3) << 16);
            u32 o = (u32)(row * PH + lane * 4) * 2;
            *(uint2*)(cAH + o) = hw;
            *(uint2*)(cAL + o) = lw;
        }
        barg(barid);

        // GEMM1: rotated*2^17
        float acc[2][8][4];
        #pragma unroll
        for (int mi = 0; mi < 2; ++mi)
            #pragma unroll
            for (int ni = 0; ni < 8; ++ni)
                #pragma unroll
                for (int p = 0; p < 4; ++p) acc[mi][ni][p] = 0.0f;
        gemm3<0>(acc, bAH, bAL, sb + SM_B1H, sb + SM_B1L, pA0, pA1, pB1);
        barg(barid);   // group done reading sA before overwrite

        // quantize accumulators -> values*512 hi/lo back into sAh/sAl
        #pragma unroll
        for (int mi = 0; mi < 2; ++mi) {
            #pragma unroll
            for (int ni = 0; ni < 8; ++ni) {
                const float* c = acc[mi][ni];
                int row0 = Rw + mi * 16 + (lane >> 2);
                int col  = Cw + ni * 8 + (lane & 3) * 2;
                u32 w[4];
                #pragma unroll
                for (int p = 0; p < 4; ++p) {
                    float v = c[p];
                    int cell = (int)fminf(fmaxf(fmaf(v, sc, nLbsc), 0.0f), 127.0f);
                    uint2 e = lut[cell];
                    int idx = (int)e.y + (v > __uint_as_float(e.x));
                    w[p] = __shfl_sync(0xffffffffu, cenw, idx);
                }
                u32 o0 = (u32)(row0 * PH + col) * 2;
                u32 o1 = o0 + (u32)(8 * PH * 2);
                *(u32*)(cAH + o0) = __byte_perm(w[0], w[1], 0x5410);
                *(u32*)(cAL + o0) = __byte_perm(w[0], w[1], 0x7632);
                *(u32*)(cAH + o1) = __byte_perm(w[2], w[3], 0x5410);
                *(u32*)(cAL + o1) = __byte_perm(w[2], w[3], 0x7632);
            }
        }
        barg(barid);

        // GEMM2: recon*2^17 = values @ Pi  (B1 read transposed via ldmatrix.trans)
        #pragma unroll
        for (int mi = 0; mi < 2; ++mi)
            #pragma unroll
            for (int ni = 0; ni < 8; ++ni)
                #pragma unroll
                for (int p = 0; p < 4; ++p) acc[mi][ni][p] = 0.0f;
        gemm3<1>(acc, bAH, bAL, sb + SM_B1H, sb + SM_B1L, pA0, pA1, pB2);

        // epilogue: scale by nq*2^-17, direct gmem stores (float2 pairs)
        float* og = out + ((size_t)t << 14);
        #pragma unroll
        for (int mi = 0; mi < 2; ++mi) {
            #pragma unroll
            for (int ni = 0; ni < 8; ++ni) {
                const float* c = acc[mi][ni];
                int row0 = Rw + mi * 16 + (lane >> 2);
                int col  = Cw + ni * 8 + (lane & 3) * 2;
                float om0 = redf[row0];
                float om1 = redf[row0 + 8];
                *(float2*)(og + (size_t)row0 * 128 + col) =
                    make_float2(c[0] * om0, c[1] * om0);
                *(float2*)(og + (size_t)(row0 + 8) * 128 + col) =
                    make_float2(c[2] * om1, c[3] * om1);
            }
        }
        barg(barid);   // protect sA/redf before next tile's writes
    }
}

extern "C" void kernel_launch(void* const* d_in, const int* in_sizes, int n_in,
                              void* d_out, int out_size)
{
    const float* x   = (const float*)d_in[0];
    const float* Pi  = (const float*)d_in[1];
    const float* cen = (const float*)d_in[2];
    const float* bnd = (const float*)d_in[3];
    float* out = (float*)d_out;

    int ntiles = in_sizes[0] / (128 * 128);      // 2048
    static int nsm = 0;
    if (nsm == 0) {       // populated on the uncaptured correctness call
        if (cudaDeviceGetAttribute(&nsm, cudaDevAttrMultiProcessorCount, 0) != cudaSuccess || nsm <= 0)
            nsm = 148;
    }
    int half = (ntiles + 1) / 2;
    int grid = nsm < half ? nsm : half;

    cudaFuncSetAttribute(tq14_kernel, cudaFuncAttributeMaxDynamicSharedMemorySize, SM_TOT);
    tq14_kernel<<<grid, NT, SM_TOT>>>(x, Pi, cen, bnd, out, ntiles);
}

// round 16
// speedup vs baseline: 2.6229x; 1.2044x over previous
#include <cuda_runtime.h>
#include <cuda_fp16.h>
#include <cstdint>

typedef unsigned int u32;
typedef unsigned long long u64;

#define NT   512
#define PH   136                    // pitch in halves (272B rows -> conflict-free ldmatrix, normal & trans)
#define TILEB (128 * PH * 2)        // 34816 B per fp16 tile

// smem byte offsets
#define SM_A    0                   // 4 A tiles: group0 {hi,lo}, group1 {hi,lo}
#define SM_B1H  (4*TILEB)           // B hi: Pi[n][k]*256   (GEMM1 normal, GEMM2 via ldmatrix.trans)
#define SM_B1L  (5*TILEB)
#define SM_RED  (6*TILEB)           // 2 x 128 floats: per-row omul = half_rt(norm)*2^-17
#define SM_LUT  (SM_RED + 1024)     // 128 x uint2 {boundary_bits, base}
#define SM_CEN  (SM_LUT + 1024)     // 16 x u32 packed (hi16|lo16) centroids*512
#define SM_BNDT (SM_CEN + 64)       // 16 floats scaled boundaries (prologue only)
#define SM_TOT  (SM_BNDT + 64)      // 211,072 B

__device__ __forceinline__ u32 s2u(const void* p) {
    u32 a; asm("{ .reg .u64 t; cvta.to.shared.u64 t, %1; cvt.u32.u64 %0, t; }" : "=r"(a) : "l"(p));
    return a;
}
__device__ __forceinline__ void ldmx4(u32 a, u32* r) {
    asm volatile("ldmatrix.sync.aligned.m8n8.x4.shared.b16 {%0,%1,%2,%3}, [%4];"
        : "=r"(r[0]), "=r"(r[1]), "=r"(r[2]), "=r"(r[3]) : "r"(a));
}
__device__ __forceinline__ void ldmx4t(u32 a, u32* r) {
    asm volatile("ldmatrix.sync.aligned.m8n8.x4.trans.shared.b16 {%0,%1,%2,%3}, [%4];"
        : "=r"(r[0]), "=r"(r[1]), "=r"(r[2]), "=r"(r[3]) : "r"(a));
}
__device__ __forceinline__ void mma16816(float* c, const u32* a, const u32* b) {
    asm volatile("mma.sync.aligned.m16n8k16.row.col.f32.f16.f16.f32 "
        "{%0,%1,%2,%3}, {%4,%5,%6,%7}, {%8,%9}, {%0,%1,%2,%3};"
        : "+f"(c[0]), "+f"(c[1]), "+f"(c[2]), "+f"(c[3])
        : "r"(a[0]), "r"(a[1]), "r"(a[2]), "r"(a[3]), "r"(b[0]), "r"(b[1]));
}
__device__ __forceinline__ void barg(int id) {
    asm volatile("bar.sync %0, %1;" :: "r"(id), "r"(256) : "memory");
}

// GEMM1: acc += Ah@Bh + Al@Bh + Ah@Bl  (3-term, B normal layout)
__device__ __forceinline__ void gemm_g1(float acc[2][8][4],
                                        u32 bah, u32 bal, u32 bbh, u32 bbl,
                                        u32 pA0, u32 pA1, const u32* pB)
{
    #pragma unroll
    for (int kc = 0; kc < 8; ++kc) {
        u32 ko = (u32)kc * 32;
        u32 ah0[4], ah1[4], al0[4], al1[4];
        ldmx4(bah + pA0 + ko, ah0);
        ldmx4(bah + pA1 + ko, ah1);
        ldmx4(bal + pA0 + ko, al0);
        ldmx4(bal + pA1 + ko, al1);
        #pragma unroll
        for (int pi = 0; pi < 4; ++pi) {
            u32 bh[4], bl[4];
            ldmx4(bbh + pB[pi] + ko, bh);
            ldmx4(bbl + pB[pi] + ko, bl);
            mma16816(acc[0][2*pi],   ah0, &bh[0]);
            mma16816(acc[0][2*pi+1], ah0, &bh[2]);
            mma16816(acc[1][2*pi],   ah1, &bh[0]);
            mma16816(acc[1][2*pi+1], ah1, &bh[2]);
            mma16816(acc[0][2*pi],   al0, &bh[0]);
            mma16816(acc[0][2*pi+1], al0, &bh[2]);
            mma16816(acc[1][2*pi],   al1, &bh[0]);
            mma16816(acc[1][2*pi+1], al1, &bh[2]);
            mma16816(acc[0][2*pi],   ah0, &bl[0]);
            mma16816(acc[0][2*pi+1], ah0, &bl[2]);
            mma16816(acc[1][2*pi],   ah1, &bl[0]);
            mma16816(acc[1][2*pi+1], ah1, &bl[2]);
        }
    }
}

// GEMM2: acc += Ah@Bh + Ah@Bl  (2-term: A = fp16 values only; B1 read transposed)
__device__ __forceinline__ void gemm_g2(float acc[2][8][4],
                                        u32 bah, u32 bbh, u32 bbl,
                                        u32 pA0, u32 pA1, const u32* pB)
{
    #pragma unroll
    for (int kc = 0; kc < 8; ++kc) {
        u32 koA = (u32)kc * 32;
        u32 koB = (u32)kc * (u32)(32 * PH);
        u32 ah0[4], ah1[4];
        ldmx4(bah + pA0 + koA, ah0);
        ldmx4(bah + pA1 + koA, ah1);
        #pragma unroll
        for (int pi = 0; pi < 4; ++pi) {
            u32 bh[4], bl[4];
            ldmx4t(bbh + pB[pi] + koB, bh);
            ldmx4t(bbl + pB[pi] + koB, bl);
            mma16816(acc[0][2*pi],   ah0, &bh[0]);
            mma16816(acc[0][2*pi+1], ah0, &bh[2]);
            mma16816(acc[1][2*pi],   ah1, &bh[0]);
            mma16816(acc[1][2*pi+1], ah1, &bh[2]);
            mma16816(acc[0][2*pi],   ah0, &bl[0]);
            mma16816(acc[0][2*pi+1], ah0, &bl[2]);
            mma16816(acc[1][2*pi],   ah1, &bl[0]);
            mma16816(acc[1][2*pi+1], ah1, &bl[2]);
        }
    }
}

__global__ void __launch_bounds__(NT, 1)
tq15_kernel(const float* __restrict__ x, const float* __restrict__ Pi,
            const float* __restrict__ cen, const float* __restrict__ bnd,
            float* __restrict__ out, int ntiles)
{
    extern __shared__ __align__(16) char smem[];
    const u32 sb   = s2u(smem);
    const int tid  = threadIdx.x;
    const int warp = tid >> 5;
    const int lane = tid & 31;
    const int gw   = warp >> 3;          // warp-group 0/1 (independent tile streams)
    const int wg   = warp & 7;           // warp within group
    float* bndT = (float*)(smem + SM_BNDT);
    const uint2* lut = (const uint2*)(smem + SM_LUT);
    float* redf = (float*)(smem + SM_RED) + gw * 128;

    // ---------------- prologue (all 512 threads) ----------------
    if (tid < 16) {
        bndT[tid] = (tid < 15) ? bnd[tid + 1] * 131072.0f : __int_as_float(0x7f800000);
        float c = cen[tid] * 512.0f;
        __half h = __float2half_rn(c);
        __half l = __float2half_rn(c - __half2float(h));
        *(u32*)(smem + SM_CEN + tid * 4) =
            (u32)__half_as_ushort(h) | ((u32)__half_as_ushort(l) << 16);
    }
    // B tile: B1[row=n][col=k] = Pi[n][k]*256, hi/lo (GEMM2 reads it transposed)
    for (int idx = tid; idx < 16384; idx += NT) {
        int row = idx >> 7, col = idx & 127;
        u32 o = (u32)(row * PH + col) * 2;
        float a = Pi[(row << 7) + col] * 256.0f;
        __half ah = __float2half_rn(a);
        *(__half*)(smem + SM_B1H + o) = ah;
        *(__half*)(smem + SM_B1L + o) = __float2half_rn(a - __half2float(ah));
    }
    __syncthreads();

    const float Lb = bndT[0], Hb = bndT[14];
    const float sc = 127.0f / (Hb - Lb);
    const float nLbsc = -Lb * sc;
    if (tid < 128) {   // LUT: at most one boundary per cell (min gap = 6.3 cells)
        float eps = 0.5f * (Hb - Lb) * (1.0f / 127.0f);
        float edge = Lb + (float)tid * ((Hb - Lb) * (1.0f / 127.0f)) - eps;
        int base = 0;
        #pragma unroll
        for (int m = 0; m < 15; ++m) base += (bndT[m] < edge);
        uint2 e; e.x = __float_as_uint(bndT[base]); e.y = (u32)base;
        *(uint2*)(smem + SM_LUT + tid * 8) = e;
    }
    __syncthreads();
    const u32 cenw = *(const u32*)(smem + SM_CEN + ((lane & 15) << 2));

    // group A-tile bases
    const u32 bAH = sb + (u32)SM_A + (u32)gw * (2 * TILEB);
    const u32 bAL = bAH + TILEB;
    char* cAH = smem + SM_A + gw * (2 * TILEB);
    char* cAL = cAH + TILEB;

    // per-lane ldmatrix address patterns (bytes)
    const int Rw = (wg >> 1) * 32;          // warp output rows
    const int Cw = (wg & 1) * 64;           // warp output cols
    const int g  = lane >> 3;
    const u32 pA0 = (u32)(((Rw + (lane & 7) + (g & 1) * 8) * PH + (lane >> 4) * 8) * 2);
    const u32 pA1 = pA0 + (u32)(16 * PH * 2);
    u32 pB1[4], pB2[4];
    #pragma unroll
    for (int pi = 0; pi < 4; ++pi) {
        pB1[pi] = (u32)(((Cw + pi * 16 + ((g >> 1) & 1) * 8 + (lane & 7)) * PH + (g & 1) * 8) * 2);
        pB2[pi] = (u32)((((g & 1) * 8 + (lane & 7)) * PH + Cw + pi * 16 + ((g >> 1) & 1) * 8) * 2);
    }
    const int barid = 1 + gw;

    float acc[2][8][4];

    // ---- phase lambdas (per group) ----
    auto ph_load = [&](int t) {   // gmem load (MLP=8 per half) + norms + hi/lo split
        const float4* src = (const float4*)x + ((size_t)t << 12);
        #pragma unroll
        for (int h = 0; h < 2; ++h) {
            float4 pf[8];
            #pragma unroll
            for (int j = 0; j < 8; ++j)
                pf[j] = src[(wg + 8 * (h * 8 + j)) * 32 + lane];
            #pragma unroll
            for (int j = 0; j < 8; ++j) {
                int row = wg + 8 * (h * 8 + j);
                float4 v = pf[j];
                float ss = v.x * v.x;
                ss = fmaf(v.y, v.y, ss); ss = fmaf(v.z, v.z, ss); ss = fmaf(v.w, v.w, ss);
                #pragma unroll
                for (int o = 16; o > 0; o >>= 1) ss += __shfl_xor_sync(0xffffffffu, ss, o);
                float n = __fsqrt_rn(ss);
                float s512 = 512.0f / (n + 1e-8f);
                if (lane == 0)
                    redf[row] = __half2float(__float2half_rn(n)) * 7.62939453125e-06f; // nq*2^-17
                float u0 = v.x * s512, u1 = v.y * s512, u2 = v.z * s512, u3 = v.w * s512;
                __half h0 = __float2half_rn(u0), h1 = __float2half_rn(u1);
                __half h2 = __float2half_rn(u2), h3 = __float2half_rn(u3);
                uint2 hw, lw;
                hw.x = (u32)__half_as_ushort(h0) | ((u32)__half_as_ushort(h1) << 16);
                hw.y = (u32)__half_as_ushort(h2) | ((u32)__half_as_ushort(h3) << 16);
                __half l0 = __float2half_rn(u0 - __half2float(h0));
                __half l1 = __float2half_rn(u1 - __half2float(h1));
                __half l2 = __float2half_rn(u2 - __half2float(h2));
                __half l3 = __float2half_rn(u3 - __half2float(h3));
                lw.x = (u32)__half_as_ushort(l0) | ((u32)__half_as_ushort(l1) << 16);
                lw.y = (u32)__half_as_ushort(l2) | ((u32)__half_as_ushort(l3) << 16);
                u32 o = (u32)(row * PH + lane * 4) * 2;
                *(uint2*)(cAH + o) = hw;
                *(uint2*)(cAL + o) = lw;
            }
        }
        barg(barid);
    };
    auto ph_g1 = [&]() {
        #pragma unroll
        for (int mi = 0; mi < 2; ++mi)
            #pragma unroll
            for (int ni = 0; ni < 8; ++ni)
                #pragma unroll
                for (int p = 0; p < 4; ++p) acc[mi][ni][p] = 0.0f;
        gemm_g1(acc, bAH, bAL, sb + SM_B1H, sb + SM_B1L, pA0, pA1, pB1);
        barg(barid);   // group done reading sA before quantize overwrites
    };
    auto ph_quant = [&]() {   // quantize acc -> fp16 values (hi only) into sAH
        #pragma unroll
        for (int mi = 0; mi < 2; ++mi) {
            #pragma unroll
            for (int ni = 0; ni < 8; ++ni) {
                const float* c = acc[mi][ni];
                int row0 = Rw + mi * 16 + (lane >> 2);
                int col  = Cw + ni * 8 + (lane & 3) * 2;
                u32 w[4];
                #pragma unroll
                for (int p = 0; p < 4; ++p) {
                    float v = c[p];
                    int cell = (int)fminf(fmaxf(fmaf(v, sc, nLbsc), 0.0f), 127.0f);
                    uint2 e = lut[cell];
                    int idx = (int)e.y + (v > __uint_as_float(e.x));
                    w[p] = __shfl_sync(0xffffffffu, cenw, idx);
                }
                u32 o0 = (u32)(row0 * PH + col) * 2;
                u32 o1 = o0 + (u32)(8 * PH * 2);
                *(u32*)(cAH + o0) = __byte_perm(w[0], w[1], 0x5410);
                *(u32*)(cAH + o1) = __byte_perm(w[2], w[3], 0x5410);
            }
        }
        barg(barid);
    };
    auto ph_g2 = [&]() {
        #pragma unroll
        for (int mi = 0; mi < 2; ++mi)
            #pragma unroll
            for (int ni = 0; ni < 8; ++ni)
                #pragma unroll
                for (int p = 0; p < 4; ++p) acc[mi][ni][p] = 0.0f;
        gemm_g2(acc, bAH, sb + SM_B1H, sb + SM_B1L, pA0, pA1, pB2);
    };
    auto ph_epi = [&](int t) {   // scale by nq*2^-17, direct gmem stores
        float* og = out + ((size_t)t << 14);
        #pragma unroll
        for (int mi = 0; mi < 2; ++mi) {
            int row0b = Rw + mi * 16 + (lane >> 2);
            float om0 = redf[row0b];
            float om1 = redf[row0b + 8];
            #pragma unroll
            for (int ni = 0; ni < 8; ++ni) {
                const float* c = acc[mi][ni];
                int col = Cw + ni * 8 + (lane & 3) * 2;
                *(float2*)(og + (size_t)row0b * 128 + col) =
                    make_float2(c[0] * om0, c[1] * om0);
                *(float2*)(og + (size_t)(row0b + 8) * 128 + col) =
                    make_float2(c[2] * om1, c[3] * om1);
            }
        }
        barg(barid);   // protect sA/redf before next tile's writes
    };

    // ---------------- per-tile loop: group gw owns stream, group1 skewed ----------------
    const int step = gridDim.x * 2;
    int t0 = blockIdx.x * 2 + gw;
    if (gw == 0) {
        for (int t = t0; t < ntiles; t += step) {
            ph_load(t); ph_g1(); ph_quant(); ph_g2(); ph_epi(t);
        }
    } else if (t0 < ntiles) {
        // rotated schedule: steady-state GEMMs sit opposite group 0's load/quantize
        ph_load(t0); ph_g1(); ph_quant();
        int t = t0;
        for (int tn = t0 + step; tn < ntiles; tn += step) {
            ph_g2(); ph_epi(t);
            t = tn;
            ph_load(t); ph_g1(); ph_quant();
        }
        ph_g2(); ph_epi(t);
    }
}

extern "C" void kernel_launch(void* const* d_in, const int* in_sizes, int n_in,
                              void* d_out, int out_size)
{
    const float* x   = (const float*)d_in[0];
    const float* Pi  = (const float*)d_in[1];
    const float* cen = (const float*)d_in[2];
    const float* bnd = (const float*)d_in[3];
    float* out = (float*)d_out;

    int ntiles = in_sizes[0] / (128 * 128);      // 2048
    static int nsm = 0;
    if (nsm == 0) {       // populated on the uncaptured correctness call
        if (cudaDeviceGetAttribute(&nsm, cudaDevAttrMultiProcessorCount, 0) != cudaSuccess || nsm <= 0)
            nsm = 148;
    }
    int half = (ntiles + 1) / 2;
    int grid = nsm < half ? nsm : half;

    cudaFuncSetAttribute(tq15_kernel, cudaFuncAttributeMaxDynamicSharedMemorySize, SM_TOT);
    tq15_kernel<<<grid, NT, SM_TOT>>>(x, Pi, cen, bnd, out, ntiles);
}